// round 8
// baseline (speedup 1.0000x reference)
#include <cuda_runtime.h>
#include <cuda_bf16.h>

#define B_    16
#define C0    8
#define T0_   32768
#define C1    64
#define T1_   16384
#define C2    128
#define T2_   8192
#define D_    64
#define T3_   4096
#define NC    512

typedef unsigned long long ull;

__device__ __forceinline__ ull pk(float lo, float hi) {
    ull r; asm("mov.b64 %0, {%1, %2};" : "=l"(r) : "f"(lo), "f"(hi)); return r;
}
__device__ __forceinline__ void upk(ull v, float& lo, float& hi) {
    asm("mov.b64 {%0, %1}, %2;" : "=f"(lo), "=f"(hi) : "l"(v));
}
__device__ __forceinline__ ull ffma2(ull a, ull b, ull c) {
    ull d; asm("fma.rn.f32x2 %0, %1, %2, %3;" : "=l"(d) : "l"(a), "l"(b), "l"(c)); return d;
}

__device__ float g_z1[B_ * C1 * T1_];
__device__ float g_z2[B_ * C2 * T2_];
__device__ float g_ze[B_ * D_ * T3_];
__device__ float g_zq[B_ * D_ * T3_];
__device__ float g_r1[B_ * C2 * T2_];
__device__ float g_r2[B_ * C1 * T1_];
__device__ int    g_hist[B_ * NC];
__device__ double g_vq_sse;
__device__ double g_rec_sse;

// duplicated {w,w} packed weights
__device__ __align__(16) ull g_w1d[8 * 64 * 8];     // [(ic*64+oc)*8+k]
__device__ __align__(16) ull g_w2d[64 * 128 * 6];   // [(ic*128+oc)*6+k]
__device__ __align__(16) ull g_w3d[128 * 64 * 4];   // [(ic*64+oc)*4+k]
__device__ __align__(16) ull g_d1d[64 * 128 * 2];
__device__ __align__(16) ull g_d2d[128 * 64 * 2];
__device__ __align__(16) ull g_d3d[64 * 8 * 2];

__global__ void k_init() {
    int i = blockIdx.x * blockDim.x + threadIdx.x;
    if (i < B_ * NC) g_hist[i] = 0;
    if (i == 0) { g_vq_sse = 0.0; g_rec_sse = 0.0; }
}

__global__ void k_prep(const float* __restrict__ w1, const float* __restrict__ w2,
                       const float* __restrict__ w3, const float* __restrict__ dw1,
                       const float* __restrict__ dw2, const float* __restrict__ dw3) {
    int tid = blockIdx.x * blockDim.x + threadIdx.x;
    int NT = gridDim.x * blockDim.x;
    for (int i = tid; i < 64 * 8 * 7; i += NT) {
        int oc = i / 56, r = i - oc * 56, ic = r / 7, k = r - ic * 7;
        float v = w1[i]; g_w1d[(ic * 64 + oc) * 8 + k] = pk(v, v);
    }
    for (int i = tid; i < 64 * 8; i += NT) g_w1d[i * 8 + 7] = 0ull;
    for (int i = tid; i < 128 * 64 * 5; i += NT) {
        int oc = i / 320, r = i - oc * 320, ic = r / 5, k = r - ic * 5;
        float v = w2[i]; g_w2d[(ic * 128 + oc) * 6 + k] = pk(v, v);
    }
    for (int i = tid; i < 64 * 128; i += NT) g_w2d[i * 6 + 5] = 0ull;
    for (int i = tid; i < 64 * 128 * 3; i += NT) {
        int oc = i / 384, r = i - oc * 384, ic = r / 3, k = r - ic * 3;
        float v = w3[i]; g_w3d[(ic * 64 + oc) * 4 + k] = pk(v, v);
    }
    for (int i = tid; i < 128 * 64; i += NT) g_w3d[i * 4 + 3] = 0ull;
    for (int i = tid; i < 64 * 128; i += NT) {
        float4 v = *(const float4*)(dw1 + i * 4);
        g_d1d[i * 2] = pk(v.w, v.z); g_d1d[i * 2 + 1] = pk(v.y, v.x);
    }
    for (int i = tid; i < 128 * 64; i += NT) {
        float4 v = *(const float4*)(dw2 + i * 4);
        g_d2d[i * 2] = pk(v.w, v.z); g_d2d[i * 2 + 1] = pk(v.y, v.x);
    }
    for (int i = tid; i < 64 * 8; i += NT) {
        float4 v = *(const float4*)(dw3 + i * 4);
        g_d3d[i * 2] = pk(v.w, v.z); g_d3d[i * 2 + 1] = pk(v.y, v.x);
    }
}

// ============================================================================
// conv1: k=7 s=2 p=3 relu. e[j]=X[2(t0+j)-2], o[j]=X[2(t0+j)-3]
// out[v]=o[v]w0+e[v]w1+o[v+1]w2+e[v+1]w3+o[v+2]w4+e[v+2]w5+o[v+3]w6
// plain-float inputs, time-pair acc2, smem-staged dup weights
// ============================================================================
__global__ __launch_bounds__(256) void k_conv1(const float* __restrict__ x,
                                               const float* __restrict__ b1) {
    __shared__ float se[8][132], so[8][132];
    __shared__ __align__(16) ull ws[8 * 64 * 8];           // 32 KB
    int b = blockIdx.y, t0 = blockIdx.x * 128;
    const float* xr = x + b * C0 * T0_;
    {
        const ulonglong2* src = (const ulonglong2*)g_w1d;
        ulonglong2* dst = (ulonglong2*)ws;
        for (int i = threadIdx.x; i < 2048; i += 256) dst[i] = src[i];
    }
    for (int idx = threadIdx.x; idx < 8 * 131; idx += 256) {
        int ic = idx / 131, j = idx - ic * 131;
        int f = 2 * (t0 + j) - 4;
        float a  = (f >= 0 && f < T0_) ? xr[ic * T0_ + f] : 0.f;
        float bb = (f + 1 >= 0 && f + 1 < T0_) ? xr[ic * T0_ + f + 1] : 0.f;
        if (j >= 1) se[ic][j - 1] = a;
        so[ic][j] = bb;
    }
    __syncthreads();
    int lane = threadIdx.x & 31, w = threadIdx.x >> 5;
    int L = lane * 4, ocb = w * 8;
    ull acc[8][2];
    #pragma unroll
    for (int i = 0; i < 8; i++) { float bv = b1[ocb + i]; ull p = pk(bv, bv); acc[i][0] = p; acc[i][1] = p; }
    #pragma unroll 1
    for (int ic = 0; ic < 8; ic++) {
        float4 e0 = *(const float4*)&se[ic][L];
        float2 e1 = *(const float2*)&se[ic][L + 4];
        float4 o0 = *(const float4*)&so[ic][L];
        float2 o1 = *(const float2*)&so[ic][L + 4];
        float o6 = so[ic][L + 6];
        ull pe01 = pk(e0.x, e0.y), pe12 = pk(e0.y, e0.z), pe23 = pk(e0.z, e0.w);
        ull pe34 = pk(e0.w, e1.x), pe45 = pk(e1.x, e1.y);
        ull po01 = pk(o0.x, o0.y), po12 = pk(o0.y, o0.z), po23 = pk(o0.z, o0.w);
        ull po34 = pk(o0.w, o1.x), po45 = pk(o1.x, o1.y), po56 = pk(o1.y, o6);
        const ulonglong2* Wp = (const ulonglong2*)&ws[(ic * 64 + ocb) * 8];
        #pragma unroll
        for (int i = 0; i < 8; i++) {
            ulonglong2 W01 = Wp[i * 4], W23 = Wp[i * 4 + 1];
            ulonglong2 W45 = Wp[i * 4 + 2], W6x = Wp[i * 4 + 3];
            ull a0 = acc[i][0], a1 = acc[i][1];
            a0 = ffma2(po01, W01.x, a0); a1 = ffma2(po23, W01.x, a1);
            a0 = ffma2(pe01, W01.y, a0); a1 = ffma2(pe23, W01.y, a1);
            a0 = ffma2(po12, W23.x, a0); a1 = ffma2(po34, W23.x, a1);
            a0 = ffma2(pe12, W23.y, a0); a1 = ffma2(pe34, W23.y, a1);
            a0 = ffma2(po23, W45.x, a0); a1 = ffma2(po45, W45.x, a1);
            a0 = ffma2(pe23, W45.y, a0); a1 = ffma2(pe45, W45.y, a1);
            a0 = ffma2(po34, W6x.x, a0); a1 = ffma2(po56, W6x.x, a1);
            acc[i][0] = a0; acc[i][1] = a1;
        }
    }
    #pragma unroll
    for (int i = 0; i < 8; i++) {
        float r0, r1, r2, r3;
        upk(acc[i][0], r0, r1); upk(acc[i][1], r2, r3);
        float4 sv = {fmaxf(r0,0.f), fmaxf(r1,0.f), fmaxf(r2,0.f), fmaxf(r3,0.f)};
        *(float4*)(g_z1 + (b * C1 + ocb + i) * T1_ + t0 + L) = sv;
    }
}

// ============================================================================
// conv2: k=5 s=2 p=2 relu. e[j]=X[2(t0+j)-2], o[j]=X[2(t0+j)-1]
// out[v]=e[v]w0+o[v]w1+e[v+1]w2+o[v+1]w3+e[v+2]w4
// 8 chunks of 8 ics; z-split ocs (64/block)
// ============================================================================
__global__ __launch_bounds__(256) void k_conv2(const float* __restrict__ b2) {
    __shared__ float se[8][132], so[8][132];
    __shared__ __align__(16) ull ws[8 * 64 * 6];           // 24 KB
    int b = blockIdx.y, t0 = blockIdx.x * 128, zz = blockIdx.z;
    const float* xin = g_z1 + b * C1 * T1_;
    int lane = threadIdx.x & 31, w = threadIdx.x >> 5;
    int L = lane * 4, ocb = zz * 64 + w * 8, ocl = w * 8;
    ull acc[8][2];
    #pragma unroll
    for (int i = 0; i < 8; i++) { float bv = b2[ocb + i]; ull p = pk(bv, bv); acc[i][0] = p; acc[i][1] = p; }
    #pragma unroll 1
    for (int ch = 0; ch < 8; ch++) {
        __syncthreads();
        {
            ulonglong2* dst = (ulonglong2*)ws;
            const ulonglong2* src = (const ulonglong2*)g_w2d;
            for (int i = threadIdx.x; i < 8 * 192; i += 256) {
                int icl = i / 192, j = i - icl * 192;
                dst[icl * 192 + j] = src[(((ch * 8 + icl) * 128 + zz * 64) * 6) / 2 + j];
            }
        }
        for (int idx = threadIdx.x; idx < 8 * 130; idx += 256) {
            int ic = idx / 130, j = idx - ic * 130;
            int icg = ch * 8 + ic;
            int f = 2 * (t0 + j) - 2;
            float a, bb;
            if (f >= 0 && f + 1 < T1_) { float2 v = *(const float2*)(xin + icg * T1_ + f); a = v.x; bb = v.y; }
            else { a = (f >= 0 && f < T1_) ? xin[icg * T1_ + f] : 0.f;
                   bb = (f + 1 >= 0 && f + 1 < T1_) ? xin[icg * T1_ + f + 1] : 0.f; }
            se[ic][j] = a; so[ic][j] = bb;
        }
        __syncthreads();
        #pragma unroll 1
        for (int ic = 0; ic < 8; ic++) {
            float4 e0 = *(const float4*)&se[ic][L];
            float2 e1 = *(const float2*)&se[ic][L + 4];
            float4 o0 = *(const float4*)&so[ic][L];
            float o4 = so[ic][L + 4];
            ull pe01 = pk(e0.x, e0.y), pe12 = pk(e0.y, e0.z), pe23 = pk(e0.z, e0.w);
            ull pe34 = pk(e0.w, e1.x), pe45 = pk(e1.x, e1.y);
            ull po01 = pk(o0.x, o0.y), po12 = pk(o0.y, o0.z), po23 = pk(o0.z, o0.w);
            ull po34 = pk(o0.w, o4);
            const ulonglong2* Wp = (const ulonglong2*)&ws[(ic * 64 + ocl) * 6];
            #pragma unroll
            for (int i = 0; i < 8; i++) {
                ulonglong2 W01 = Wp[i * 3], W23 = Wp[i * 3 + 1], W4x = Wp[i * 3 + 2];
                ull a0 = acc[i][0], a1 = acc[i][1];
                a0 = ffma2(pe01, W01.x, a0); a1 = ffma2(pe23, W01.x, a1);
                a0 = ffma2(po01, W01.y, a0); a1 = ffma2(po23, W01.y, a1);
                a0 = ffma2(pe12, W23.x, a0); a1 = ffma2(pe34, W23.x, a1);
                a0 = ffma2(po12, W23.y, a0); a1 = ffma2(po34, W23.y, a1);
                a0 = ffma2(pe23, W4x.x, a0); a1 = ffma2(pe45, W4x.x, a1);
                acc[i][0] = a0; acc[i][1] = a1;
            }
        }
    }
    #pragma unroll
    for (int i = 0; i < 8; i++) {
        float r0, r1, r2, r3;
        upk(acc[i][0], r0, r1); upk(acc[i][1], r2, r3);
        float4 sv = {fmaxf(r0,0.f), fmaxf(r1,0.f), fmaxf(r2,0.f), fmaxf(r3,0.f)};
        *(float4*)(g_z2 + (b * C2 + ocb + i) * T2_ + t0 + L) = sv;
    }
}

// ============================================================================
// conv3: k=3 s=2 p=1. e[j]=X[2(t0+j)], o[j]=X[2(t0+j)-1]
// out[v]=o[v]w0+e[v]w1+o[v+1]w2.  16 chunks of 8 ics
// ============================================================================
__global__ __launch_bounds__(256) void k_conv3(const float* __restrict__ b3) {
    __shared__ float se[8][132], so[8][132];
    __shared__ __align__(16) ull ws[8 * 64 * 4];           // 16 KB
    int b = blockIdx.y, t0 = blockIdx.x * 128;
    const float* xin = g_z2 + b * C2 * T2_;
    int lane = threadIdx.x & 31, w = threadIdx.x >> 5;
    int L = lane * 4, ocb = w * 8;
    ull acc[8][2];
    #pragma unroll
    for (int i = 0; i < 8; i++) { float bv = b3[ocb + i]; ull p = pk(bv, bv); acc[i][0] = p; acc[i][1] = p; }
    #pragma unroll 1
    for (int ch = 0; ch < 16; ch++) {
        __syncthreads();
        {
            ulonglong2* dst = (ulonglong2*)ws;
            const ulonglong2* src = (const ulonglong2*)g_w3d;
            for (int i = threadIdx.x; i < 8 * 128; i += 256)
                dst[i] = src[(ch * 8) * 128 + i];
        }
        for (int idx = threadIdx.x; idx < 8 * 130; idx += 256) {
            int ic = idx / 130, j = idx - ic * 130;
            int icg = ch * 8 + ic;
            int f = 2 * (t0 + j) - 2;
            float a, bb;
            if (f >= 0 && f + 1 < T2_) { float2 v = *(const float2*)(xin + icg * T2_ + f); a = v.x; bb = v.y; }
            else { a = (f >= 0 && f < T2_) ? xin[icg * T2_ + f] : 0.f;
                   bb = (f + 1 >= 0 && f + 1 < T2_) ? xin[icg * T2_ + f + 1] : 0.f; }
            if (j >= 1) se[ic][j - 1] = a;
            so[ic][j] = bb;
        }
        __syncthreads();
        #pragma unroll 1
        for (int ic = 0; ic < 8; ic++) {
            float4 e0 = *(const float4*)&se[ic][L];
            float4 o0 = *(const float4*)&so[ic][L];
            float o4 = so[ic][L + 4];
            ull pe01 = pk(e0.x, e0.y), pe23 = pk(e0.z, e0.w);
            ull po01 = pk(o0.x, o0.y), po12 = pk(o0.y, o0.z), po23 = pk(o0.z, o0.w);
            ull po34 = pk(o0.w, o4);
            const ulonglong2* Wp = (const ulonglong2*)&ws[(ic * 64 + ocb) * 4];
            #pragma unroll
            for (int i = 0; i < 8; i++) {
                ulonglong2 W01 = Wp[i * 2], W2x = Wp[i * 2 + 1];
                ull a0 = acc[i][0], a1 = acc[i][1];
                a0 = ffma2(po01, W01.x, a0); a1 = ffma2(po23, W01.x, a1);
                a0 = ffma2(pe01, W01.y, a0); a1 = ffma2(pe23, W01.y, a1);
                a0 = ffma2(po12, W2x.x, a0); a1 = ffma2(po34, W2x.x, a1);
                acc[i][0] = a0; acc[i][1] = a1;
            }
        }
    }
    #pragma unroll
    for (int i = 0; i < 8; i++) {
        float r0, r1, r2, r3;
        upk(acc[i][0], r0, r1); upk(acc[i][1], r2, r3);
        float4 sv = {r0, r1, r2, r3};
        *(float4*)(g_ze + (b * D_ + ocb + i) * T3_ + t0 + L) = sv;
    }
}

__global__ __launch_bounds__(256) void k_quant(const float* __restrict__ cb) {
    __shared__ __align__(16) float scb[128 * 64];
    __shared__ float snorm[128];
    __shared__ int   shist[NC];
    __shared__ float sred[8];
    int tid = threadIdx.x;
    int g = blockIdx.x * 256 + tid;
    int b = g >> 12, t = g & 4095;
    for (int i = tid; i < NC; i += 256) shist[i] = 0;
    float z[64];
    const float* zp = g_ze + b * D_ * T3_ + t;
    #pragma unroll
    for (int d = 0; d < 64; d++) z[d] = zp[d * T3_];
    float zz = 0.f;
    #pragma unroll
    for (int d = 0; d < 64; d++) zz += z[d] * z[d];
    ull z2[32];
    #pragma unroll
    for (int q = 0; q < 32; q++) z2[q] = pk(z[2 * q], z[2 * q + 1]);
    float best = 3.4e38f;
    int bi = 0;
    for (int ch = 0; ch < 4; ch++) {
        __syncthreads();
        for (int i = tid; i < 128 * 64; i += 256) scb[i] = cb[ch * 8192 + i];
        __syncthreads();
        for (int c = tid; c < 128; c += 256) {
            float n = 0.f;
            for (int d = 0; d < 64; d++) { float v = scb[c * 64 + d]; n += v * v; }
            snorm[c] = n;
        }
        __syncthreads();
        for (int c = 0; c < 128; c++) {
            const ulonglong2* cp = (const ulonglong2*)(scb + c * 64);
            ull d0 = 0ull, d1 = 0ull;
            #pragma unroll
            for (int q = 0; q < 16; q++) {
                ulonglong2 pv = cp[q];
                d0 = ffma2(z2[2 * q], pv.x, d0);
                d1 = ffma2(z2[2 * q + 1], pv.y, d1);
            }
            float a0, a1, a2, a3;
            upk(d0, a0, a1); upk(d1, a2, a3);
            float dot = (a0 + a1) + (a2 + a3);
            float d2 = zz - 2.f * dot + snorm[c];
            if (d2 < best) { best = d2; bi = ch * 128 + c; }
        }
    }
    const float* cbest = cb + bi * 64;
    float* zqp = g_zq + b * D_ * T3_ + t;
    float sse = 0.f;
    #pragma unroll
    for (int d = 0; d < 64; d++) {
        float cv = __ldg(&cbest[d]);
        float df = z[d] - cv;
        sse += df * df;
        zqp[d * T3_] = cv;
    }
    atomicAdd(&shist[bi], 1);
    int lane = tid & 31, w = tid >> 5;
    #pragma unroll
    for (int off = 16; off; off >>= 1) sse += __shfl_down_sync(0xffffffffu, sse, off);
    if (lane == 0) sred[w] = sse;
    __syncthreads();
    if (tid < 8) {
        float v = sred[tid];
        #pragma unroll
        for (int off = 4; off; off >>= 1) v += __shfl_down_sync(0xffu, v, off);
        if (tid == 0) atomicAdd(&g_vq_sse, (double)v);
    }
    __syncthreads();
    for (int i = tid; i < NC; i += 256)
        if (shist[i]) atomicAdd(&g_hist[b * NC + i], shist[i]);
}

__global__ void k_cond(const float* __restrict__ cb, float* __restrict__ out) {
    int b = blockIdx.x, d = threadIdx.x;
    float sum = 0.f;
    for (int c = 0; c < NC; c++)
        sum += (float)g_hist[b * NC + c] * cb[c * 64 + d];
    out[b * 64 + d] = sum * (1.f / (float)T3_);
}

// decT1: z_q -> r1[16,128,8192], relu. z-split ocs, 8 ocs/warp
__global__ __launch_bounds__(256) void k_dec1(const float* __restrict__ db1) {
    __shared__ float s[64][132];
    int b = blockIdx.y, m0 = blockIdx.x * 128, zz = blockIdx.z;
    const float* xin = g_zq + b * D_ * T3_;
    for (int idx = threadIdx.x; idx < 64 * 130; idx += 256) {
        int ic = idx / 130, j = idx - ic * 130;
        int gg = m0 - 1 + j;
        s[ic][j] = (gg >= 0 && gg < T3_) ? xin[ic * T3_ + gg] : 0.f;
    }
    __syncthreads();
    int lane = threadIdx.x & 31, w = threadIdx.x >> 5;
    int M0 = lane * 4, ocb = zz * 64 + w * 8;
    ull acc[8][4];
    #pragma unroll
    for (int i = 0; i < 8; i++) {
        float bv = db1[ocb + i]; ull p = pk(bv, bv);
        #pragma unroll
        for (int j = 0; j < 4; j++) acc[i][j] = p;
    }
    #pragma unroll 1
    for (int ic = 0; ic < 64; ic++) {
        float4 v = *(const float4*)&s[ic][M0];
        float2 v2 = *(const float2*)&s[ic][M0 + 4];
        ull p0 = pk(v.x, v.y), p1 = pk(v.y, v.z), p2 = pk(v.z, v.w);
        ull p3 = pk(v.w, v2.x), p4 = pk(v2.x, v2.y);
        const ulonglong2* Wp = (const ulonglong2*)(g_d1d + (ic * 128 + ocb) * 2);
        #pragma unroll
        for (int i = 0; i < 8; i++) {
            ulonglong2 W = Wp[i];
            acc[i][0] = ffma2(p1, W.y, ffma2(p0, W.x, acc[i][0]));
            acc[i][1] = ffma2(p2, W.y, ffma2(p1, W.x, acc[i][1]));
            acc[i][2] = ffma2(p3, W.y, ffma2(p2, W.x, acc[i][2]));
            acc[i][3] = ffma2(p4, W.y, ffma2(p3, W.x, acc[i][3]));
        }
    }
    #pragma unroll
    for (int i = 0; i < 8; i++) {
        float r[8];
        #pragma unroll
        for (int j = 0; j < 4; j++) upk(acc[i][j], r[2 * j], r[2 * j + 1]);
        float* op = g_r1 + (b * C2 + ocb + i) * T2_ + 2 * m0 + lane * 8;
        float4 s0 = {fmaxf(r[0],0.f), fmaxf(r[1],0.f), fmaxf(r[2],0.f), fmaxf(r[3],0.f)};
        float4 s1 = {fmaxf(r[4],0.f), fmaxf(r[5],0.f), fmaxf(r[6],0.f), fmaxf(r[7],0.f)};
        *(float4*)op = s0; *(float4*)(op + 4) = s1;
    }
}

// decT2: r1 -> r2[16,64,16384], relu. 8 ocs/warp, 2 ic chunks of 64
__global__ __launch_bounds__(256) void k_dec2(const float* __restrict__ db2) {
    __shared__ float s[64][132];
    int b = blockIdx.y, m0 = blockIdx.x * 128;
    const float* xin = g_r1 + b * C2 * T2_;
    int lane = threadIdx.x & 31, w = threadIdx.x >> 5;
    int M0 = lane * 4, ocb = w * 8;
    ull acc[8][4];
    #pragma unroll
    for (int i = 0; i < 8; i++) {
        float bv = db2[ocb + i]; ull p = pk(bv, bv);
        #pragma unroll
        for (int j = 0; j < 4; j++) acc[i][j] = p;
    }
    #pragma unroll 1
    for (int ch = 0; ch < 2; ch++) {
        __syncthreads();
        for (int idx = threadIdx.x; idx < 64 * 130; idx += 256) {
            int ic = idx / 130, j = idx - ic * 130;
            int gg = m0 - 1 + j;
            s[ic][j] = (gg >= 0 && gg < T2_) ? xin[(ch * 64 + ic) * T2_ + gg] : 0.f;
        }
        __syncthreads();
        #pragma unroll 1
        for (int ic = 0; ic < 64; ic++) {
            int icg = ch * 64 + ic;
            float4 v = *(const float4*)&s[ic][M0];
            float2 v2 = *(const float2*)&s[ic][M0 + 4];
            ull p0 = pk(v.x, v.y), p1 = pk(v.y, v.z), p2 = pk(v.z, v.w);
            ull p3 = pk(v.w, v2.x), p4 = pk(v2.x, v2.y);
            const ulonglong2* Wp = (const ulonglong2*)(g_d2d + (icg * 64 + ocb) * 2);
            #pragma unroll
            for (int i = 0; i < 8; i++) {
                ulonglong2 W = Wp[i];
                acc[i][0] = ffma2(p1, W.y, ffma2(p0, W.x, acc[i][0]));
                acc[i][1] = ffma2(p2, W.y, ffma2(p1, W.x, acc[i][1]));
                acc[i][2] = ffma2(p3, W.y, ffma2(p2, W.x, acc[i][2]));
                acc[i][3] = ffma2(p4, W.y, ffma2(p3, W.x, acc[i][3]));
            }
        }
    }
    #pragma unroll
    for (int i = 0; i < 8; i++) {
        float r[8];
        #pragma unroll
        for (int j = 0; j < 4; j++) upk(acc[i][j], r[2 * j], r[2 * j + 1]);
        float* op = g_r2 + (b * C1 + ocb + i) * T1_ + 2 * m0 + lane * 8;
        float4 s0 = {fmaxf(r[0],0.f), fmaxf(r[1],0.f), fmaxf(r[2],0.f), fmaxf(r[3],0.f)};
        float4 s1 = {fmaxf(r[4],0.f), fmaxf(r[5],0.f), fmaxf(r[6],0.f), fmaxf(r[7],0.f)};
        *(float4*)op = s0; *(float4*)(op + 4) = s1;
    }
}

// decT3 fused with recon-MSE
__global__ __launch_bounds__(256) void k_dec3(const float* __restrict__ db3,
                                              const float* __restrict__ x) {
    __shared__ float s[64][132];
    __shared__ float sred[8];
    int b = blockIdx.y, m0 = blockIdx.x * 128;
    const float* xin = g_r2 + b * C1 * T1_;
    for (int idx = threadIdx.x; idx < 64 * 130; idx += 256) {
        int ic = idx / 130, j = idx - ic * 130;
        int gg = m0 - 1 + j;
        s[ic][j] = (gg >= 0 && gg < T1_) ? xin[ic * T1_ + gg] : 0.f;
    }
    __syncthreads();
    int lane = threadIdx.x & 31, w = threadIdx.x >> 5;
    int M0 = lane * 4, oc = w;
    ull acc[4];
    { float bv = db3[oc]; ull p = pk(bv, bv);
      #pragma unroll
      for (int j = 0; j < 4; j++) acc[j] = p; }
    #pragma unroll 1
    for (int ic = 0; ic < 64; ic++) {
        float4 v = *(const float4*)&s[ic][M0];
        float2 v2 = *(const float2*)&s[ic][M0 + 4];
        ull p0 = pk(v.x, v.y), p1 = pk(v.y, v.z), p2 = pk(v.z, v.w);
        ull p3 = pk(v.w, v2.x), p4 = pk(v2.x, v2.y);
        ulonglong2 W = *(const ulonglong2*)(g_d3d + (ic * 8 + oc) * 2);
        acc[0] = ffma2(p1, W.y, ffma2(p0, W.x, acc[0]));
        acc[1] = ffma2(p2, W.y, ffma2(p1, W.x, acc[1]));
        acc[2] = ffma2(p3, W.y, ffma2(p2, W.x, acc[2]));
        acc[3] = ffma2(p4, W.y, ffma2(p3, W.x, acc[3]));
    }
    float r[8];
    #pragma unroll
    for (int j = 0; j < 4; j++) upk(acc[j], r[2 * j], r[2 * j + 1]);
    const float* xr = x + (b * C0 + oc) * T0_ + 2 * m0 + lane * 8;
    float4 xa = *(const float4*)xr;
    float4 xb = *(const float4*)(xr + 4);
    float d0 = r[0]-xa.x, d1 = r[1]-xa.y, d2 = r[2]-xa.z, d3 = r[3]-xa.w;
    float d4 = r[4]-xb.x, d5 = r[5]-xb.y, d6 = r[6]-xb.z, d7 = r[7]-xb.w;
    float ssq = d0*d0 + d1*d1 + d2*d2 + d3*d3 + d4*d4 + d5*d5 + d6*d6 + d7*d7;
    #pragma unroll
    for (int off = 16; off; off >>= 1) ssq += __shfl_down_sync(0xffffffffu, ssq, off);
    if (lane == 0) sred[w] = ssq;
    __syncthreads();
    if (threadIdx.x < 8) {
        float v = sred[threadIdx.x];
        #pragma unroll
        for (int off = 4; off; off >>= 1) v += __shfl_down_sync(0xffu, v, off);
        if (threadIdx.x == 0) atomicAdd(&g_rec_sse, (double)v);
    }
}

__global__ void k_fin(float* __restrict__ out, int out_size) {
    if (out_size >= 1027) {
        float vq = (float)(g_vq_sse / (double)(B_ * D_ * T3_));
        out[1024] = vq;
        out[1025] = vq;
        out[1026] = (float)(g_rec_sse / (double)(B_ * C0 * T0_));
    }
}

extern "C" void kernel_launch(void* const* d_in, const int* in_sizes, int n_in,
                              void* d_out, int out_size) {
    const float* x   = (const float*)d_in[0];
    const float* w1  = (const float*)d_in[1];
    const float* b1  = (const float*)d_in[2];
    const float* w2  = (const float*)d_in[3];
    const float* b2  = (const float*)d_in[4];
    const float* w3  = (const float*)d_in[5];
    const float* b3  = (const float*)d_in[6];
    const float* cb  = (const float*)d_in[7];
    const float* dw1 = (const float*)d_in[8];
    const float* db1 = (const float*)d_in[9];
    const float* dw2 = (const float*)d_in[10];
    const float* db2 = (const float*)d_in[11];
    const float* dw3 = (const float*)d_in[12];
    const float* db3 = (const float*)d_in[13];
    float* out = (float*)d_out;

    k_init<<<32, 256>>>();
    k_prep<<<160, 256>>>(w1, w2, w3, dw1, dw2, dw3);
    k_conv1<<<dim3(T1_ / 128, B_), 256>>>(x, b1);
    k_conv2<<<dim3(T2_ / 128, B_, 2), 256>>>(b2);
    k_conv3<<<dim3(T3_ / 128, B_), 256>>>(b3);
    k_quant<<<(B_ * T3_) / 256, 256>>>(cb);
    k_cond<<<B_, 64>>>(cb, out);
    k_dec1<<<dim3(T3_ / 128, B_, 2), 256>>>(db1);
    k_dec2<<<dim3(T2_ / 128, B_), 256>>>(db2);
    k_dec3<<<dim3(T1_ / 128, B_), 256>>>(db3, x);
    k_fin<<<1, 1>>>(out, out_size);
}

// round 9
// speedup vs baseline: 1.0772x; 1.0772x over previous
#include <cuda_runtime.h>
#include <cuda_bf16.h>

#define B_    16
#define C0    8
#define T0_   32768
#define C1    64
#define T1_   16384
#define C2    128
#define T2_   8192
#define D_    64
#define T3_   4096
#define NC    512

typedef unsigned long long ull;

__device__ __forceinline__ ull pk(float lo, float hi) {
    ull r; asm("mov.b64 %0, {%1, %2};" : "=l"(r) : "f"(lo), "f"(hi)); return r;
}
__device__ __forceinline__ void upk(ull v, float& lo, float& hi) {
    asm("mov.b64 {%0, %1}, %2;" : "=f"(lo), "=f"(hi) : "l"(v));
}
__device__ __forceinline__ ull ffma2(ull a, ull b, ull c) {
    ull d; asm("fma.rn.f32x2 %0, %1, %2, %3;" : "=l"(d) : "l"(a), "l"(b), "l"(c)); return d;
}

__device__ float g_z1[B_ * C1 * T1_];
__device__ float g_z2[B_ * C2 * T2_];
__device__ float g_ze[B_ * D_ * T3_];
__device__ float g_zq[B_ * D_ * T3_];
__device__ float g_r1[B_ * C2 * T2_];
__device__ float g_r2[B_ * C1 * T1_];
__device__ int    g_hist[B_ * NC];
__device__ double g_vq_sse;
__device__ double g_rec_sse;

// duplicated {w,w} packed weights
__device__ __align__(16) ull g_w1d[8 * 64 * 8];
__device__ __align__(16) ull g_w2d[64 * 128 * 6];
__device__ __align__(16) ull g_w3d[128 * 64 * 4];
__device__ __align__(16) ull g_d1d[64 * 128 * 2];
__device__ __align__(16) ull g_d2d[128 * 64 * 2];
__device__ __align__(16) ull g_d3d[64 * 8 * 2];

__global__ void k_init() {
    int i = blockIdx.x * blockDim.x + threadIdx.x;
    if (i < B_ * NC) g_hist[i] = 0;
    if (i == 0) { g_vq_sse = 0.0; g_rec_sse = 0.0; }
}

__global__ void k_prep(const float* __restrict__ w1, const float* __restrict__ w2,
                       const float* __restrict__ w3, const float* __restrict__ dw1,
                       const float* __restrict__ dw2, const float* __restrict__ dw3) {
    int tid = blockIdx.x * blockDim.x + threadIdx.x;
    int NT = gridDim.x * blockDim.x;
    for (int i = tid; i < 64 * 8 * 7; i += NT) {
        int oc = i / 56, r = i - oc * 56, ic = r / 7, k = r - ic * 7;
        float v = w1[i]; g_w1d[(ic * 64 + oc) * 8 + k] = pk(v, v);
    }
    for (int i = tid; i < 64 * 8; i += NT) g_w1d[i * 8 + 7] = 0ull;
    for (int i = tid; i < 128 * 64 * 5; i += NT) {
        int oc = i / 320, r = i - oc * 320, ic = r / 5, k = r - ic * 5;
        float v = w2[i]; g_w2d[(ic * 128 + oc) * 6 + k] = pk(v, v);
    }
    for (int i = tid; i < 64 * 128; i += NT) g_w2d[i * 6 + 5] = 0ull;
    for (int i = tid; i < 64 * 128 * 3; i += NT) {
        int oc = i / 384, r = i - oc * 384, ic = r / 3, k = r - ic * 3;
        float v = w3[i]; g_w3d[(ic * 64 + oc) * 4 + k] = pk(v, v);
    }
    for (int i = tid; i < 128 * 64; i += NT) g_w3d[i * 4 + 3] = 0ull;
    for (int i = tid; i < 64 * 128; i += NT) {
        float4 v = *(const float4*)(dw1 + i * 4);
        g_d1d[i * 2] = pk(v.w, v.z); g_d1d[i * 2 + 1] = pk(v.y, v.x);
    }
    for (int i = tid; i < 128 * 64; i += NT) {
        float4 v = *(const float4*)(dw2 + i * 4);
        g_d2d[i * 2] = pk(v.w, v.z); g_d2d[i * 2 + 1] = pk(v.y, v.x);
    }
    for (int i = tid; i < 64 * 8; i += NT) {
        float4 v = *(const float4*)(dw3 + i * 4);
        g_d3d[i * 2] = pk(v.w, v.z); g_d3d[i * 2 + 1] = pk(v.y, v.x);
    }
}

// ============================================================================
// conv1: k=7 s=2 p=3 relu (unchanged from r8 — small kernel)
// ============================================================================
__global__ __launch_bounds__(256) void k_conv1(const float* __restrict__ x,
                                               const float* __restrict__ b1) {
    __shared__ float se[8][132], so[8][132];
    __shared__ __align__(16) ull ws[8 * 64 * 8];
    int b = blockIdx.y, t0 = blockIdx.x * 128;
    const float* xr = x + b * C0 * T0_;
    {
        const ulonglong2* src = (const ulonglong2*)g_w1d;
        ulonglong2* dst = (ulonglong2*)ws;
        for (int i = threadIdx.x; i < 2048; i += 256) dst[i] = src[i];
    }
    for (int idx = threadIdx.x; idx < 8 * 131; idx += 256) {
        int ic = idx / 131, j = idx - ic * 131;
        int f = 2 * (t0 + j) - 4;
        float a  = (f >= 0 && f < T0_) ? xr[ic * T0_ + f] : 0.f;
        float bb = (f + 1 >= 0 && f + 1 < T0_) ? xr[ic * T0_ + f + 1] : 0.f;
        if (j >= 1) se[ic][j - 1] = a;
        so[ic][j] = bb;
    }
    __syncthreads();
    int lane = threadIdx.x & 31, w = threadIdx.x >> 5;
    int L = lane * 4, ocb = w * 8;
    ull acc[8][2];
    #pragma unroll
    for (int i = 0; i < 8; i++) { float bv = b1[ocb + i]; ull p = pk(bv, bv); acc[i][0] = p; acc[i][1] = p; }
    #pragma unroll 1
    for (int ic = 0; ic < 8; ic++) {
        float4 e0 = *(const float4*)&se[ic][L];
        float2 e1 = *(const float2*)&se[ic][L + 4];
        float4 o0 = *(const float4*)&so[ic][L];
        float2 o1 = *(const float2*)&so[ic][L + 4];
        float o6 = so[ic][L + 6];
        ull pe01 = pk(e0.x, e0.y), pe12 = pk(e0.y, e0.z), pe23 = pk(e0.z, e0.w);
        ull pe34 = pk(e0.w, e1.x), pe45 = pk(e1.x, e1.y);
        ull po01 = pk(o0.x, o0.y), po12 = pk(o0.y, o0.z), po23 = pk(o0.z, o0.w);
        ull po34 = pk(o0.w, o1.x), po45 = pk(o1.x, o1.y), po56 = pk(o1.y, o6);
        const ulonglong2* Wp = (const ulonglong2*)&ws[(ic * 64 + ocb) * 8];
        #pragma unroll
        for (int i = 0; i < 8; i++) {
            ulonglong2 W01 = Wp[i * 4], W23 = Wp[i * 4 + 1];
            ulonglong2 W45 = Wp[i * 4 + 2], W6x = Wp[i * 4 + 3];
            ull a0 = acc[i][0], a1 = acc[i][1];
            a0 = ffma2(po01, W01.x, a0); a1 = ffma2(po23, W01.x, a1);
            a0 = ffma2(pe01, W01.y, a0); a1 = ffma2(pe23, W01.y, a1);
            a0 = ffma2(po12, W23.x, a0); a1 = ffma2(po34, W23.x, a1);
            a0 = ffma2(pe12, W23.y, a0); a1 = ffma2(pe34, W23.y, a1);
            a0 = ffma2(po23, W45.x, a0); a1 = ffma2(po45, W45.x, a1);
            a0 = ffma2(pe23, W45.y, a0); a1 = ffma2(pe45, W45.y, a1);
            a0 = ffma2(po34, W6x.x, a0); a1 = ffma2(po56, W6x.x, a1);
            acc[i][0] = a0; acc[i][1] = a1;
        }
    }
    #pragma unroll
    for (int i = 0; i < 8; i++) {
        float r0, r1, r2, r3;
        upk(acc[i][0], r0, r1); upk(acc[i][1], r2, r3);
        float4 sv = {fmaxf(r0,0.f), fmaxf(r1,0.f), fmaxf(r2,0.f), fmaxf(r3,0.f)};
        *(float4*)(g_z1 + (b * C1 + ocb + i) * T1_ + t0 + L) = sv;
    }
}

// ============================================================================
// conv2: k=5 s=2 p=2 relu. TT=8 (256-wide tile), TO=8, 8 chunks of 8 ics, z-split
// e[j]=X[2(t0+j)-2], o[j]=X[2(t0+j)-1]
// out[v]=e[v]w0+o[v]w1+e[v+1]w2+o[v+1]w3+e[v+2]w4
// ============================================================================
__global__ __launch_bounds__(256) void k_conv2(const float* __restrict__ b2) {
    __shared__ float se[8][264], so[8][264];
    __shared__ __align__(16) ull ws[8 * 64 * 6];          // 24 KB
    int b = blockIdx.y, t0 = blockIdx.x * 256, zz = blockIdx.z;
    const float* xin = g_z1 + b * C1 * T1_;
    int lane = threadIdx.x & 31, w = threadIdx.x >> 5;
    int L = lane * 8, ocb = zz * 64 + w * 8, ocl = w * 8;
    ull acc[8][4];
    #pragma unroll
    for (int i = 0; i < 8; i++) {
        float bv = b2[ocb + i]; ull p = pk(bv, bv);
        #pragma unroll
        for (int v = 0; v < 4; v++) acc[i][v] = p;
    }
    #pragma unroll 1
    for (int ch = 0; ch < 8; ch++) {
        __syncthreads();
        {
            ulonglong2* dst = (ulonglong2*)ws;
            const ulonglong2* src = (const ulonglong2*)g_w2d;
            for (int i = threadIdx.x; i < 1536; i += 256) {
                int icl = i / 192, j = i - icl * 192;
                dst[i] = src[((ch * 8 + icl) * 128 + zz * 64) * 3 + j];
            }
        }
        for (int idx = threadIdx.x; idx < 8 * 258; idx += 256) {
            int ic = idx / 258, j = idx - ic * 258;
            int icg = ch * 8 + ic;
            int f = 2 * (t0 + j) - 2;
            float a, bb;
            if (f >= 0 && f + 1 < T1_) { float2 v = *(const float2*)(xin + icg * T1_ + f); a = v.x; bb = v.y; }
            else { a = (f >= 0 && f < T1_) ? xin[icg * T1_ + f] : 0.f;
                   bb = (f + 1 >= 0 && f + 1 < T1_) ? xin[icg * T1_ + f + 1] : 0.f; }
            se[ic][j] = a; so[ic][j] = bb;
        }
        __syncthreads();
        #pragma unroll 1
        for (int ic = 0; ic < 8; ic++) {
            float4 E0 = *(const float4*)&se[ic][L];
            float4 E4 = *(const float4*)&se[ic][L + 4];
            float2 E8 = *(const float2*)&se[ic][L + 8];
            float4 O0 = *(const float4*)&so[ic][L];
            float4 O4 = *(const float4*)&so[ic][L + 4];
            float  O8 = so[ic][L + 8];
            ull peA[5], peU[4], poA[4], poU[4];
            peA[0] = pk(E0.x, E0.y); peA[1] = pk(E0.z, E0.w); peA[2] = pk(E4.x, E4.y);
            peA[3] = pk(E4.z, E4.w); peA[4] = pk(E8.x, E8.y);
            peU[0] = pk(E0.y, E0.z); peU[1] = pk(E0.w, E4.x);
            peU[2] = pk(E4.y, E4.z); peU[3] = pk(E4.w, E8.x);
            poA[0] = pk(O0.x, O0.y); poA[1] = pk(O0.z, O0.w);
            poA[2] = pk(O4.x, O4.y); poA[3] = pk(O4.z, O4.w);
            poU[0] = pk(O0.y, O0.z); poU[1] = pk(O0.w, O4.x);
            poU[2] = pk(O4.y, O4.z); poU[3] = pk(O4.w, O8);
            const ulonglong2* Wp = (const ulonglong2*)&ws[(ic * 64 + ocl) * 6];
            #pragma unroll
            for (int i = 0; i < 8; i++) {
                ulonglong2 W01 = Wp[i * 3], W23 = Wp[i * 3 + 1], W4x = Wp[i * 3 + 2];
                #pragma unroll
                for (int v = 0; v < 4; v++) {
                    ull a = acc[i][v];
                    a = ffma2(peA[v],     W01.x, a);
                    a = ffma2(poA[v],     W01.y, a);
                    a = ffma2(peU[v],     W23.x, a);
                    a = ffma2(poU[v],     W23.y, a);
                    a = ffma2(peA[v + 1], W4x.x, a);
                    acc[i][v] = a;
                }
            }
        }
    }
    #pragma unroll
    for (int i = 0; i < 8; i++) {
        float r[8];
        #pragma unroll
        for (int v = 0; v < 4; v++) upk(acc[i][v], r[2 * v], r[2 * v + 1]);
        float* op = g_z2 + (b * C2 + ocb + i) * T2_ + t0 + L;
        float4 s0 = {fmaxf(r[0],0.f), fmaxf(r[1],0.f), fmaxf(r[2],0.f), fmaxf(r[3],0.f)};
        float4 s1 = {fmaxf(r[4],0.f), fmaxf(r[5],0.f), fmaxf(r[6],0.f), fmaxf(r[7],0.f)};
        *(float4*)op = s0; *(float4*)(op + 4) = s1;
    }
}

// ============================================================================
// conv3: k=3 s=2 p=1. TT=8, TO=8, 16 chunks of 8 ics
// e[j]=X[2(t0+j)] (shifted store), o[j]=X[2(t0+j)-1]
// out[v]=o[v]w0+e[v]w1+o[v+1]w2
// ============================================================================
__global__ __launch_bounds__(256) void k_conv3(const float* __restrict__ b3) {
    __shared__ float se[8][264], so[8][264];
    __shared__ __align__(16) ull ws[8 * 64 * 4];          // 16 KB
    int b = blockIdx.y, t0 = blockIdx.x * 256;
    const float* xin = g_z2 + b * C2 * T2_;
    int lane = threadIdx.x & 31, w = threadIdx.x >> 5;
    int L = lane * 8, ocb = w * 8;
    ull acc[8][4];
    #pragma unroll
    for (int i = 0; i < 8; i++) {
        float bv = b3[ocb + i]; ull p = pk(bv, bv);
        #pragma unroll
        for (int v = 0; v < 4; v++) acc[i][v] = p;
    }
    #pragma unroll 1
    for (int ch = 0; ch < 16; ch++) {
        __syncthreads();
        {
            ulonglong2* dst = (ulonglong2*)ws;
            const ulonglong2* src = (const ulonglong2*)g_w3d;
            for (int i = threadIdx.x; i < 1024; i += 256)
                dst[i] = src[ch * 1024 + i];
        }
        for (int idx = threadIdx.x; idx < 8 * 258; idx += 256) {
            int ic = idx / 258, j = idx - ic * 258;
            int icg = ch * 8 + ic;
            int f = 2 * (t0 + j) - 2;
            float a, bb;
            if (f >= 0 && f + 1 < T2_) { float2 v = *(const float2*)(xin + icg * T2_ + f); a = v.x; bb = v.y; }
            else { a = (f >= 0 && f < T2_) ? xin[icg * T2_ + f] : 0.f;
                   bb = (f + 1 >= 0 && f + 1 < T2_) ? xin[icg * T2_ + f + 1] : 0.f; }
            if (j >= 1) se[ic][j - 1] = a;
            so[ic][j] = bb;
        }
        __syncthreads();
        #pragma unroll 1
        for (int ic = 0; ic < 8; ic++) {
            float4 E0 = *(const float4*)&se[ic][L];
            float4 E4 = *(const float4*)&se[ic][L + 4];
            float4 O0 = *(const float4*)&so[ic][L];
            float4 O4 = *(const float4*)&so[ic][L + 4];
            float  O8 = so[ic][L + 8];
            ull peA[4], poA[4], poU[4];
            peA[0] = pk(E0.x, E0.y); peA[1] = pk(E0.z, E0.w);
            peA[2] = pk(E4.x, E4.y); peA[3] = pk(E4.z, E4.w);
            poA[0] = pk(O0.x, O0.y); poA[1] = pk(O0.z, O0.w);
            poA[2] = pk(O4.x, O4.y); poA[3] = pk(O4.z, O4.w);
            poU[0] = pk(O0.y, O0.z); poU[1] = pk(O0.w, O4.x);
            poU[2] = pk(O4.y, O4.z); poU[3] = pk(O4.w, O8);
            const ulonglong2* Wp = (const ulonglong2*)&ws[(ic * 64 + ocb) * 4];
            #pragma unroll
            for (int i = 0; i < 8; i++) {
                ulonglong2 W01 = Wp[i * 2], W2x = Wp[i * 2 + 1];
                #pragma unroll
                for (int v = 0; v < 4; v++) {
                    ull a = acc[i][v];
                    a = ffma2(poA[v], W01.x, a);
                    a = ffma2(peA[v], W01.y, a);
                    a = ffma2(poU[v], W2x.x, a);
                    acc[i][v] = a;
                }
            }
        }
    }
    #pragma unroll
    for (int i = 0; i < 8; i++) {
        float r[8];
        #pragma unroll
        for (int v = 0; v < 4; v++) upk(acc[i][v], r[2 * v], r[2 * v + 1]);
        float* op = g_ze + (b * D_ + ocb + i) * T3_ + t0 + L;
        float4 s0 = {r[0], r[1], r[2], r[3]};
        float4 s1 = {r[4], r[5], r[6], r[7]};
        *(float4*)op = s0; *(float4*)(op + 4) = s1;
    }
}

__global__ __launch_bounds__(256) void k_quant(const float* __restrict__ cb) {
    __shared__ __align__(16) float scb[128 * 64];
    __shared__ float snorm[128];
    __shared__ int   shist[NC];
    __shared__ float sred[8];
    int tid = threadIdx.x;
    int g = blockIdx.x * 256 + tid;
    int b = g >> 12, t = g & 4095;
    for (int i = tid; i < NC; i += 256) shist[i] = 0;
    float z[64];
    const float* zp = g_ze + b * D_ * T3_ + t;
    #pragma unroll
    for (int d = 0; d < 64; d++) z[d] = zp[d * T3_];
    float zz = 0.f;
    #pragma unroll
    for (int d = 0; d < 64; d++) zz += z[d] * z[d];
    ull z2[32];
    #pragma unroll
    for (int q = 0; q < 32; q++) z2[q] = pk(z[2 * q], z[2 * q + 1]);
    float best = 3.4e38f;
    int bi = 0;
    for (int ch = 0; ch < 4; ch++) {
        __syncthreads();
        for (int i = tid; i < 128 * 64; i += 256) scb[i] = cb[ch * 8192 + i];
        __syncthreads();
        for (int c = tid; c < 128; c += 256) {
            float n = 0.f;
            for (int d = 0; d < 64; d++) { float v = scb[c * 64 + d]; n += v * v; }
            snorm[c] = n;
        }
        __syncthreads();
        for (int c = 0; c < 128; c++) {
            const ulonglong2* cp = (const ulonglong2*)(scb + c * 64);
            ull d0 = 0ull, d1 = 0ull;
            #pragma unroll
            for (int q = 0; q < 16; q++) {
                ulonglong2 pv = cp[q];
                d0 = ffma2(z2[2 * q], pv.x, d0);
                d1 = ffma2(z2[2 * q + 1], pv.y, d1);
            }
            float a0, a1, a2, a3;
            upk(d0, a0, a1); upk(d1, a2, a3);
            float dot = (a0 + a1) + (a2 + a3);
            float d2 = zz - 2.f * dot + snorm[c];
            if (d2 < best) { best = d2; bi = ch * 128 + c; }
        }
    }
    const float* cbest = cb + bi * 64;
    float* zqp = g_zq + b * D_ * T3_ + t;
    float sse = 0.f;
    #pragma unroll
    for (int d = 0; d < 64; d++) {
        float cv = __ldg(&cbest[d]);
        float df = z[d] - cv;
        sse += df * df;
        zqp[d * T3_] = cv;
    }
    atomicAdd(&shist[bi], 1);
    int lane = tid & 31, w = tid >> 5;
    #pragma unroll
    for (int off = 16; off; off >>= 1) sse += __shfl_down_sync(0xffffffffu, sse, off);
    if (lane == 0) sred[w] = sse;
    __syncthreads();
    if (tid < 8) {
        float v = sred[tid];
        #pragma unroll
        for (int off = 4; off; off >>= 1) v += __shfl_down_sync(0xffu, v, off);
        if (tid == 0) atomicAdd(&g_vq_sse, (double)v);
    }
    __syncthreads();
    for (int i = tid; i < NC; i += 256)
        if (shist[i]) atomicAdd(&g_hist[b * NC + i], shist[i]);
}

__global__ void k_cond(const float* __restrict__ cb, float* __restrict__ out) {
    int b = blockIdx.x, d = threadIdx.x;
    float sum = 0.f;
    for (int c = 0; c < NC; c++)
        sum += (float)g_hist[b * NC + c] * cb[c * 64 + d];
    out[b * 64 + d] = sum * (1.f / (float)T3_);
}

// decT1: z_q -> r1[16,128,8192], relu. z-split ocs, smem-staged weights, 4 chunks of 16 ics
__global__ __launch_bounds__(256) void k_dec1(const float* __restrict__ db1) {
    __shared__ float s[16][132];
    __shared__ __align__(16) ull ws[16 * 64 * 2];         // 16 KB
    int b = blockIdx.y, m0 = blockIdx.x * 128, zz = blockIdx.z;
    const float* xin = g_zq + b * D_ * T3_;
    int lane = threadIdx.x & 31, w = threadIdx.x >> 5;
    int M0 = lane * 4, ocb = zz * 64 + w * 8, ocl = w * 8;
    ull acc[8][4];
    #pragma unroll
    for (int i = 0; i < 8; i++) {
        float bv = db1[ocb + i]; ull p = pk(bv, bv);
        #pragma unroll
        for (int j = 0; j < 4; j++) acc[i][j] = p;
    }
    #pragma unroll 1
    for (int ch = 0; ch < 4; ch++) {
        __syncthreads();
        {
            ulonglong2* dst = (ulonglong2*)ws;
            const ulonglong2* src = (const ulonglong2*)g_d1d;
            for (int i = threadIdx.x; i < 1024; i += 256) {
                int icl = i >> 6, j = i & 63;
                dst[i] = src[(ch * 16 + icl) * 128 + zz * 64 + j];
            }
        }
        for (int idx = threadIdx.x; idx < 16 * 130; idx += 256) {
            int ic = idx / 130, j = idx - ic * 130;
            int gg = m0 - 1 + j;
            s[ic][j] = (gg >= 0 && gg < T3_) ? xin[(ch * 16 + ic) * T3_ + gg] : 0.f;
        }
        __syncthreads();
        #pragma unroll 1
        for (int ic = 0; ic < 16; ic++) {
            float4 v = *(const float4*)&s[ic][M0];
            float2 v2 = *(const float2*)&s[ic][M0 + 4];
            ull p0 = pk(v.x, v.y), p1 = pk(v.y, v.z), p2 = pk(v.z, v.w);
            ull p3 = pk(v.w, v2.x), p4 = pk(v2.x, v2.y);
            const ulonglong2* Wp = (const ulonglong2*)&ws[(ic * 64 + ocl) * 2];
            #pragma unroll
            for (int i = 0; i < 8; i++) {
                ulonglong2 W = Wp[i];
                acc[i][0] = ffma2(p1, W.y, ffma2(p0, W.x, acc[i][0]));
                acc[i][1] = ffma2(p2, W.y, ffma2(p1, W.x, acc[i][1]));
                acc[i][2] = ffma2(p3, W.y, ffma2(p2, W.x, acc[i][2]));
                acc[i][3] = ffma2(p4, W.y, ffma2(p3, W.x, acc[i][3]));
            }
        }
    }
    #pragma unroll
    for (int i = 0; i < 8; i++) {
        float r[8];
        #pragma unroll
        for (int j = 0; j < 4; j++) upk(acc[i][j], r[2 * j], r[2 * j + 1]);
        float* op = g_r1 + (b * C2 + ocb + i) * T2_ + 2 * m0 + lane * 8;
        float4 s0 = {fmaxf(r[0],0.f), fmaxf(r[1],0.f), fmaxf(r[2],0.f), fmaxf(r[3],0.f)};
        float4 s1 = {fmaxf(r[4],0.f), fmaxf(r[5],0.f), fmaxf(r[6],0.f), fmaxf(r[7],0.f)};
        *(float4*)op = s0; *(float4*)(op + 4) = s1;
    }
}

// decT2: r1 -> r2[16,64,16384], relu. smem-staged weights, 8 chunks of 16 ics
__global__ __launch_bounds__(256) void k_dec2(const float* __restrict__ db2) {
    __shared__ float s[16][132];
    __shared__ __align__(16) ull ws[16 * 64 * 2];         // 16 KB
    int b = blockIdx.y, m0 = blockIdx.x * 128;
    const float* xin = g_r1 + b * C2 * T2_;
    int lane = threadIdx.x & 31, w = threadIdx.x >> 5;
    int M0 = lane * 4, ocb = w * 8;
    ull acc[8][4];
    #pragma unroll
    for (int i = 0; i < 8; i++) {
        float bv = db2[ocb + i]; ull p = pk(bv, bv);
        #pragma unroll
        for (int j = 0; j < 4; j++) acc[i][j] = p;
    }
    #pragma unroll 1
    for (int ch = 0; ch < 8; ch++) {
        __syncthreads();
        {
            ulonglong2* dst = (ulonglong2*)ws;
            const ulonglong2* src = (const ulonglong2*)g_d2d;
            for (int i = threadIdx.x; i < 1024; i += 256)
                dst[i] = src[ch * 1024 + i];
        }
        for (int idx = threadIdx.x; idx < 16 * 130; idx += 256) {
            int ic = idx / 130, j = idx - ic * 130;
            int gg = m0 - 1 + j;
            s[ic][j] = (gg >= 0 && gg < T2_) ? xin[(ch * 16 + ic) * T2_ + gg] : 0.f;
        }
        __syncthreads();
        #pragma unroll 1
        for (int ic = 0; ic < 16; ic++) {
            float4 v = *(const float4*)&s[ic][M0];
            float2 v2 = *(const float2*)&s[ic][M0 + 4];
            ull p0 = pk(v.x, v.y), p1 = pk(v.y, v.z), p2 = pk(v.z, v.w);
            ull p3 = pk(v.w, v2.x), p4 = pk(v2.x, v2.y);
            const ulonglong2* Wp = (const ulonglong2*)&ws[(ic * 64 + ocb) * 2];
            #pragma unroll
            for (int i = 0; i < 8; i++) {
                ulonglong2 W = Wp[i];
                acc[i][0] = ffma2(p1, W.y, ffma2(p0, W.x, acc[i][0]));
                acc[i][1] = ffma2(p2, W.y, ffma2(p1, W.x, acc[i][1]));
                acc[i][2] = ffma2(p3, W.y, ffma2(p2, W.x, acc[i][2]));
                acc[i][3] = ffma2(p4, W.y, ffma2(p3, W.x, acc[i][3]));
            }
        }
    }
    #pragma unroll
    for (int i = 0; i < 8; i++) {
        float r[8];
        #pragma unroll
        for (int j = 0; j < 4; j++) upk(acc[i][j], r[2 * j], r[2 * j + 1]);
        float* op = g_r2 + (b * C1 + ocb + i) * T1_ + 2 * m0 + lane * 8;
        float4 s0 = {fmaxf(r[0],0.f), fmaxf(r[1],0.f), fmaxf(r[2],0.f), fmaxf(r[3],0.f)};
        float4 s1 = {fmaxf(r[4],0.f), fmaxf(r[5],0.f), fmaxf(r[6],0.f), fmaxf(r[7],0.f)};
        *(float4*)op = s0; *(float4*)(op + 4) = s1;
    }
}

// decT3 fused with recon-MSE; weights fully staged (8 KB)
__global__ __launch_bounds__(256) void k_dec3(const float* __restrict__ db3,
                                              const float* __restrict__ x) {
    __shared__ float s[64][132];
    __shared__ __align__(16) ull ws[64 * 8 * 2];          // 8 KB
    __shared__ float sred[8];
    int b = blockIdx.y, m0 = blockIdx.x * 128;
    const float* xin = g_r2 + b * C1 * T1_;
    {
        ulonglong2* dst = (ulonglong2*)ws;
        const ulonglong2* src = (const ulonglong2*)g_d3d;
        for (int i = threadIdx.x; i < 512; i += 256) dst[i] = src[i];
    }
    for (int idx = threadIdx.x; idx < 64 * 130; idx += 256) {
        int ic = idx / 130, j = idx - ic * 130;
        int gg = m0 - 1 + j;
        s[ic][j] = (gg >= 0 && gg < T1_) ? xin[ic * T1_ + gg] : 0.f;
    }
    __syncthreads();
    int lane = threadIdx.x & 31, w = threadIdx.x >> 5;
    int M0 = lane * 4, oc = w;
    ull acc[4];
    { float bv = db3[oc]; ull p = pk(bv, bv);
      #pragma unroll
      for (int j = 0; j < 4; j++) acc[j] = p; }
    #pragma unroll 1
    for (int ic = 0; ic < 64; ic++) {
        float4 v = *(const float4*)&s[ic][M0];
        float2 v2 = *(const float2*)&s[ic][M0 + 4];
        ull p0 = pk(v.x, v.y), p1 = pk(v.y, v.z), p2 = pk(v.z, v.w);
        ull p3 = pk(v.w, v2.x), p4 = pk(v2.x, v2.y);
        ulonglong2 W = *(const ulonglong2*)&ws[(ic * 8 + oc) * 2];
        acc[0] = ffma2(p1, W.y, ffma2(p0, W.x, acc[0]));
        acc[1] = ffma2(p2, W.y, ffma2(p1, W.x, acc[1]));
        acc[2] = ffma2(p3, W.y, ffma2(p2, W.x, acc[2]));
        acc[3] = ffma2(p4, W.y, ffma2(p3, W.x, acc[3]));
    }
    float r[8];
    #pragma unroll
    for (int j = 0; j < 4; j++) upk(acc[j], r[2 * j], r[2 * j + 1]);
    const float* xr = x + (b * C0 + oc) * T0_ + 2 * m0 + lane * 8;
    float4 xa = *(const float4*)xr;
    float4 xb = *(const float4*)(xr + 4);
    float d0 = r[0]-xa.x, d1 = r[1]-xa.y, d2 = r[2]-xa.z, d3 = r[3]-xa.w;
    float d4 = r[4]-xb.x, d5 = r[5]-xb.y, d6 = r[6]-xb.z, d7 = r[7]-xb.w;
    float ssq = d0*d0 + d1*d1 + d2*d2 + d3*d3 + d4*d4 + d5*d5 + d6*d6 + d7*d7;
    #pragma unroll
    for (int off = 16; off; off >>= 1) ssq += __shfl_down_sync(0xffffffffu, ssq, off);
    if (lane == 0) sred[w] = ssq;
    __syncthreads();
    if (threadIdx.x < 8) {
        float v = sred[threadIdx.x];
        #pragma unroll
        for (int off = 4; off; off >>= 1) v += __shfl_down_sync(0xffu, v, off);
        if (threadIdx.x == 0) atomicAdd(&g_rec_sse, (double)v);
    }
}

__global__ void k_fin(float* __restrict__ out, int out_size) {
    if (out_size >= 1027) {
        float vq = (float)(g_vq_sse / (double)(B_ * D_ * T3_));
        out[1024] = vq;
        out[1025] = vq;
        out[1026] = (float)(g_rec_sse / (double)(B_ * C0 * T0_));
    }
}

extern "C" void kernel_launch(void* const* d_in, const int* in_sizes, int n_in,
                              void* d_out, int out_size) {
    const float* x   = (const float*)d_in[0];
    const float* w1  = (const float*)d_in[1];
    const float* b1  = (const float*)d_in[2];
    const float* w2  = (const float*)d_in[3];
    const float* b2  = (const float*)d_in[4];
    const float* w3  = (const float*)d_in[5];
    const float* b3  = (const float*)d_in[6];
    const float* cb  = (const float*)d_in[7];
    const float* dw1 = (const float*)d_in[8];
    const float* db1 = (const float*)d_in[9];
    const float* dw2 = (const float*)d_in[10];
    const float* db2 = (const float*)d_in[11];
    const float* dw3 = (const float*)d_in[12];
    const float* db3 = (const float*)d_in[13];
    float* out = (float*)d_out;

    k_init<<<32, 256>>>();
    k_prep<<<160, 256>>>(w1, w2, w3, dw1, dw2, dw3);
    k_conv1<<<dim3(T1_ / 128, B_), 256>>>(x, b1);
    k_conv2<<<dim3(T2_ / 256, B_, 2), 256>>>(b2);
    k_conv3<<<dim3(T3_ / 256, B_), 256>>>(b3);
    k_quant<<<(B_ * T3_) / 256, 256>>>(cb);
    k_cond<<<B_, 64>>>(cb, out);
    k_dec1<<<dim3(T3_ / 128, B_, 2), 256>>>(db1);
    k_dec2<<<dim3(T2_ / 128, B_), 256>>>(db2);
    k_dec3<<<dim3(T1_ / 128, B_), 256>>>(db3, x);
    k_fin<<<1, 1>>>(out, out_size);
}